// round 1
// baseline (speedup 1.0000x reference)
#include <cuda_runtime.h>
#include <math.h>

#define BSZ   2
#define TLEN  4096
#define DIMD  1024
#define NST   16
#define MROWS (BSZ*TLEN)   // 8192

// ---------------- scratch (static device allocations; no cudaMalloc) --------
__device__ float g_xz[(size_t)MROWS * 2 * DIMD];   // (m, 2048): x_in | z
__device__ float g_xactT[(size_t)DIMD * MROWS];    // (d, m)  conv+silu output
__device__ float g_szT[(size_t)DIMD * MROWS];      // (d, m)  silu(z)
__device__ float g_dtT[(size_t)DIMD * MROWS];      // (d, m)  softplus dt
__device__ float g_BC[(size_t)MROWS * 2 * NST];    // (m, 32) B|C
__device__ float g_yT[(size_t)DIMD * MROWS];       // (d, m)  scan output * silu(z)

// ---------------- GEMM: C = A*B -------------------------------------------
// AT_STORE: A is stored transposed (K x M row-major), else (M x K row-major)
// CT_STORE: write C transposed (N x M), else (M x N)
// EPI: 0 = none, 1 = softplus(acc + bias[col])
template<int EPI>
__device__ __forceinline__ float epi_apply(float v, float b) {
    if (EPI == 1) {
        v += b;
        v = (v > 20.f) ? v : log1pf(expf(v));
    }
    return v;
}

template<bool AT_STORE, bool CT_STORE, int EPI>
__global__ __launch_bounds__(256) void sgemm_kernel(
    const float* __restrict__ A, const float* __restrict__ B,
    float* __restrict__ C, const float* __restrict__ bias,
    int M, int N, int K)
{
    __shared__ __align__(16) float As[8][128];
    __shared__ __align__(16) float Bs[8][128];
    const int tid = threadIdx.x;
    const int m0 = blockIdx.y * 128;
    const int n0 = blockIdx.x * 128;

    float acc[8][8];
    #pragma unroll
    for (int i = 0; i < 8; i++)
        #pragma unroll
        for (int j = 0; j < 8; j++) acc[i][j] = 0.f;

    const int aRow = tid >> 1, aCol = (tid & 1) * 4;   // normal A load
    const int aK = tid >> 5, aM = (tid & 31) * 4;      // transposed A load
    const int bK = tid >> 5, bN = (tid & 31) * 4;
    const int tr = (tid >> 4) * 8, tc = (tid & 15) * 8;

    for (int k0 = 0; k0 < K; k0 += 8) {
        if (AT_STORE) {
            float4 v = *(const float4*)(A + (size_t)(k0 + aK) * M + m0 + aM);
            *(float4*)&As[aK][aM] = v;
        } else {
            float4 v = *(const float4*)(A + (size_t)(m0 + aRow) * K + k0 + aCol);
            As[aCol + 0][aRow] = v.x;
            As[aCol + 1][aRow] = v.y;
            As[aCol + 2][aRow] = v.z;
            As[aCol + 3][aRow] = v.w;
        }
        float4 bv = *(const float4*)(B + (size_t)(k0 + bK) * N + n0 + bN);
        *(float4*)&Bs[bK][bN] = bv;
        __syncthreads();

        #pragma unroll
        for (int kk = 0; kk < 8; kk++) {
            float4 a0 = *(const float4*)&As[kk][tr];
            float4 a1 = *(const float4*)&As[kk][tr + 4];
            float4 b0 = *(const float4*)&Bs[kk][tc];
            float4 b1 = *(const float4*)&Bs[kk][tc + 4];
            float ar[8] = {a0.x, a0.y, a0.z, a0.w, a1.x, a1.y, a1.z, a1.w};
            float br[8] = {b0.x, b0.y, b0.z, b0.w, b1.x, b1.y, b1.z, b1.w};
            #pragma unroll
            for (int i = 0; i < 8; i++)
                #pragma unroll
                for (int j = 0; j < 8; j++)
                    acc[i][j] = fmaf(ar[i], br[j], acc[i][j]);
        }
        __syncthreads();
    }

    if (CT_STORE) {
        #pragma unroll
        for (int j = 0; j < 8; j++) {
            float bb = (EPI == 1) ? bias[n0 + tc + j] : 0.f;
            #pragma unroll
            for (int i = 0; i < 8; i += 4) {
                float4 v;
                v.x = epi_apply<EPI>(acc[i + 0][j], bb);
                v.y = epi_apply<EPI>(acc[i + 1][j], bb);
                v.z = epi_apply<EPI>(acc[i + 2][j], bb);
                v.w = epi_apply<EPI>(acc[i + 3][j], bb);
                *(float4*)(C + (size_t)(n0 + tc + j) * M + m0 + tr + i) = v;
            }
        }
    } else {
        #pragma unroll
        for (int i = 0; i < 8; i++) {
            #pragma unroll
            for (int j = 0; j < 8; j += 4) {
                float4 v;
                v.x = epi_apply<EPI>(acc[i][j + 0], (EPI==1)?bias[n0+tc+j+0]:0.f);
                v.y = epi_apply<EPI>(acc[i][j + 1], (EPI==1)?bias[n0+tc+j+1]:0.f);
                v.z = epi_apply<EPI>(acc[i][j + 2], (EPI==1)?bias[n0+tc+j+2]:0.f);
                v.w = epi_apply<EPI>(acc[i][j + 3], (EPI==1)?bias[n0+tc+j+3]:0.f);
                *(float4*)(C + (size_t)(m0 + tr + i) * N + n0 + tc + j) = v;
            }
        }
    }
}

// ---------------- depthwise causal conv (k=4) + SiLU, plus silu(z); write transposed
__global__ __launch_bounds__(256) void conv_kernel(
    const float* __restrict__ cw, const float* __restrict__ cb)
{
    __shared__ float sx[32][69];   // 69 stride: conflict-free
    __shared__ float sz[32][65];
    const int tid = threadIdx.x;
    const int d0 = blockIdx.x * 32;
    const int t0 = blockIdx.y * 64;
    const int b  = blockIdx.z;

    for (int idx = tid; idx < 32 * 67; idx += 256) {
        int tt = idx >> 5, dd = idx & 31;
        int t = t0 + tt - 3;
        float v = 0.f;
        if (t >= 0) v = g_xz[((size_t)(b * TLEN + t)) * (2 * DIMD) + d0 + dd];
        sx[dd][tt] = v;
    }
    for (int idx = tid; idx < 32 * 64; idx += 256) {
        int tt = idx >> 5, dd = idx & 31;
        sz[dd][tt] = g_xz[((size_t)(b * TLEN + t0 + tt)) * (2 * DIMD) + DIMD + d0 + dd];
    }
    __syncthreads();

    const int dd = tid >> 3;
    const int tb = (tid & 7) * 8;
    const int d  = d0 + dd;
    const float w0 = cw[d * 4 + 0], w1 = cw[d * 4 + 1];
    const float w2 = cw[d * 4 + 2], w3 = cw[d * 4 + 3];
    const float bsv = cb[d];
    const size_t obase = (size_t)d * MROWS + (size_t)b * TLEN + t0 + tb;
    #pragma unroll
    for (int i = 0; i < 8; i++) {
        int tt = tb + i;
        float a = bsv + w0 * sx[dd][tt] + w1 * sx[dd][tt + 1]
                      + w2 * sx[dd][tt + 2] + w3 * sx[dd][tt + 3];
        g_xactT[obase + i] = a / (1.f + __expf(-a));
        float z = sz[dd][tt];
        g_szT[obase + i] = z / (1.f + __expf(-z));
    }
}

// ---------------- BC = x_act @ W_x (K-major A), out (m, 32) -----------------
__global__ __launch_bounds__(256) void bc_kernel(const float* __restrict__ Wx)
{
    __shared__ float xs[32][64];
    __shared__ float ws[32][32];
    const int tid = threadIdx.x;
    const int m0 = blockIdx.x * 64;
    const int n = tid & 31;
    const int mb = (tid >> 5) * 8;
    float acc[8];
    #pragma unroll
    for (int i = 0; i < 8; i++) acc[i] = 0.f;

    for (int d0 = 0; d0 < DIMD; d0 += 32) {
        #pragma unroll
        for (int r = 0; r < 8; r++) {
            int idx = tid + r * 256;
            int dd = idx >> 6, mm = idx & 63;
            xs[dd][mm] = g_xactT[(size_t)(d0 + dd) * MROWS + m0 + mm];
        }
        #pragma unroll
        for (int r = 0; r < 4; r++) {
            int idx = tid + r * 256;
            int dd = idx >> 5, nn = idx & 31;
            ws[dd][nn] = Wx[(d0 + dd) * 32 + nn];
        }
        __syncthreads();
        #pragma unroll
        for (int dd = 0; dd < 32; dd++) {
            float w = ws[dd][n];
            #pragma unroll
            for (int i = 0; i < 8; i++)
                acc[i] = fmaf(xs[dd][mb + i], w, acc[i]);
        }
        __syncthreads();
    }
    #pragma unroll
    for (int i = 0; i < 8; i++)
        g_BC[(size_t)(m0 + mb + i) * 32 + n] = acc[i];
}

// ---------------- selective scan: one thread per (b, d, n) ------------------
__global__ __launch_bounds__(256) void scan_kernel(
    const float* __restrict__ A_log, const float* __restrict__ Dpar)
{
    const int g = blockIdx.x * blockDim.x + threadIdx.x;  // 0..32767
    const int n = g & (NST - 1);
    const int bd = g >> 4;
    const int d = bd & (DIMD - 1);
    const int b = bd >> 10;

    const float Adn = -expf(A_log[d * NST + n]);
    const float Dp = Dpar[d];
    const size_t rb = (size_t)d * MROWS + (size_t)b * TLEN;
    const float* bc = g_BC + (size_t)b * TLEN * 32;

    float h = 0.f;
    for (int t0 = 0; t0 < TLEN; t0 += 16) {
        float dtv = g_dtT[rb + t0 + n];   // lane n holds t0+n
        float xv  = g_xactT[rb + t0 + n];
        float ybuf = 0.f;
        #pragma unroll
        for (int k = 0; k < 16; k++) {
            float dtk = __shfl_sync(0xffffffffu, dtv, k, 16);
            float xk  = __shfl_sync(0xffffffffu, xv,  k, 16);
            float Bv = bc[(t0 + k) * 32 + n];
            float Cv = bc[(t0 + k) * 32 + NST + n];
            float a = __expf(dtk * Adn);
            h = fmaf(a, h, dtk * Bv * xk);
            float p = h * Cv;
            p += __shfl_xor_sync(0xffffffffu, p, 1, 16);
            p += __shfl_xor_sync(0xffffffffu, p, 2, 16);
            p += __shfl_xor_sync(0xffffffffu, p, 4, 16);
            p += __shfl_xor_sync(0xffffffffu, p, 8, 16);
            if (k == n) ybuf = fmaf(Dp, xk, p);   // lane n keeps t0+n
        }
        float sv = g_szT[rb + t0 + n];
        g_yT[rb + t0 + n] = ybuf * sv;            // coalesced store
    }
}

// ---------------- launch ----------------------------------------------------
extern "C" void kernel_launch(void* const* d_in, const int* in_sizes, int n_in,
                              void* d_out, int out_size)
{
    const float* x      = (const float*)d_in[0];
    const float* W_in   = (const float*)d_in[1];
    const float* conv_w = (const float*)d_in[2];
    const float* conv_b = (const float*)d_in[3];
    const float* A_log  = (const float*)d_in[4];
    const float* D_par  = (const float*)d_in[5];
    const float* W_x    = (const float*)d_in[6];
    const float* W_dt   = (const float*)d_in[7];
    const float* b_dt   = (const float*)d_in[8];
    const float* W_out  = (const float*)d_in[9];
    float* out = (float*)d_out;

    float *p_xz, *p_xactT, *p_dtT, *p_yT;
    cudaGetSymbolAddress((void**)&p_xz,    g_xz);
    cudaGetSymbolAddress((void**)&p_xactT, g_xactT);
    cudaGetSymbolAddress((void**)&p_dtT,   g_dtT);
    cudaGetSymbolAddress((void**)&p_yT,    g_yT);

    // 1) xz = x @ W_in   (8192 x 2048 x 1024)
    {
        dim3 grid(2 * DIMD / 128, MROWS / 128);
        sgemm_kernel<false, false, 0><<<grid, 256>>>(x, W_in, p_xz, nullptr,
                                                     MROWS, 2 * DIMD, DIMD);
    }
    // 2) depthwise conv + SiLU (-> xactT), silu(z) (-> szT)
    {
        dim3 grid(DIMD / 32, TLEN / 64, BSZ);
        conv_kernel<<<grid, 256>>>(conv_w, conv_b);
    }
    // 3) BC = x_act @ W_x  (8192 x 32)
    bc_kernel<<<MROWS / 64, 256>>>(W_x);
    // 4) dtT = softplus(x_act @ W_dt + b_dt)^T
    {
        dim3 grid(DIMD / 128, MROWS / 128);
        sgemm_kernel<true, true, 1><<<grid, 256>>>(p_xactT, W_dt, p_dtT, b_dt,
                                                   MROWS, DIMD, DIMD);
    }
    // 5) selective scan -> yT (includes *silu(z))
    scan_kernel<<<(BSZ * DIMD * NST) / 256, 256>>>(A_log, D_par);
    // 6) out = y @ W_out
    {
        dim3 grid(DIMD / 128, MROWS / 128);
        sgemm_kernel<true, false, 0><<<grid, 256>>>(p_yT, W_out, out, nullptr,
                                                    MROWS, DIMD, DIMD);
    }
}

// round 2
// speedup vs baseline: 1.8216x; 1.8216x over previous
#include <cuda_runtime.h>
#include <math.h>
#include <stdint.h>

#define BSZ   2
#define TLEN  4096
#define DIMD  1024
#define NST   16
#define MROWS (BSZ*TLEN)   // 8192

// ---------------- scratch (static device allocations; no cudaMalloc) --------
__device__ float g_xz[(size_t)MROWS * 2 * DIMD];   // (m, 2048): x_in | z
__device__ float g_xactT[(size_t)DIMD * MROWS];    // (d, m)  conv+silu output
__device__ float g_szT[(size_t)DIMD * MROWS];      // (d, m)  silu(z)
__device__ float g_dtT[(size_t)DIMD * MROWS];      // (d, m)  softplus dt
__device__ float g_BC[(size_t)MROWS * 2 * NST];    // (m, 32) B|C
__device__ float g_yT[(size_t)DIMD * MROWS];       // (d, m)  scan output * silu(z)

// ---------------- tf32 helpers ---------------------------------------------
__device__ __forceinline__ float to_tf32(float x) {
    uint32_t u;
    asm("cvt.rna.tf32.f32 %0, %1;" : "=r"(u) : "f"(x));
    return __uint_as_float(u);
}

__device__ __forceinline__ void mma_tf32(float* d, const uint32_t* a, const uint32_t* b) {
    asm volatile(
        "mma.sync.aligned.m16n8k8.row.col.f32.tf32.tf32.f32 "
        "{%0,%1,%2,%3}, {%4,%5,%6,%7}, {%8,%9}, {%0,%1,%2,%3};\n"
        : "+f"(d[0]), "+f"(d[1]), "+f"(d[2]), "+f"(d[3])
        : "r"(a[0]), "r"(a[1]), "r"(a[2]), "r"(a[3]), "r"(b[0]), "r"(b[1]));
}

__device__ __forceinline__ float softplus_f(float v) {
    return (v > 20.f) ? v : log1pf(expf(v));
}

// ---------------- TF32 tensor GEMM: C[M][N] = A @ B ------------------------
// A_KM: A is stored [K][M] row-major (i.e. "A transposed"); else [M][K].
// B is always [K][N] row-major. C written [M][N].
// EPI: 0 = none, 1 = softplus(acc + bias[row]).
template<bool A_KM, int EPI>
__global__ __launch_bounds__(256) void tgemm(
    const float* __restrict__ A, const float* __restrict__ B,
    float* __restrict__ C, const float* __restrict__ bias,
    int M, int N, int K)
{
    constexpr int ASZ = A_KM ? 16 * 136 : 128 * 20;
    __shared__ float As[2][ASZ];
    __shared__ float Bs[2][16 * 136];

    const int tid  = threadIdx.x;
    const int warp = tid >> 5, lane = tid & 31;
    const int m0 = blockIdx.y * 128, n0 = blockIdx.x * 128;
    const int wm = (warp >> 1) * 32;   // 4 warp rows
    const int wn = (warp & 1) * 64;    // 2 warp cols
    const int r  = lane >> 2, cq = lane & 3;

    float acc[2][8][4];
    #pragma unroll
    for (int i = 0; i < 2; i++)
        #pragma unroll
        for (int j = 0; j < 8; j++)
            #pragma unroll
            for (int k = 0; k < 4; k++) acc[i][j][k] = 0.f;

    // global-load index precompute
    const int ak = tid >> 5;           // A_KM: k row (0..7); +8 for 2nd
    const int am = (tid & 31) * 4;     // A_KM: m offset
    const int tm = tid >> 2;           // !A_KM: m (0..63); +64 for 2nd
    const int tk = (tid & 3) * 4;      // !A_KM: k offset
    const int bk = tid >> 5;
    const int bn = (tid & 31) * 4;

    float4 ra0, ra1, rb0, rb1;

    auto ldg = [&](int kt) {
        if (A_KM) {
            const float* p = A + (size_t)(kt * 16 + ak) * M + m0 + am;
            ra0 = *(const float4*)p;
            ra1 = *(const float4*)(p + (size_t)8 * M);
        } else {
            const float* p = A + (size_t)(m0 + tm) * K + kt * 16 + tk;
            ra0 = *(const float4*)p;
            ra1 = *(const float4*)(p + (size_t)64 * K);
        }
        const float* q = B + (size_t)(kt * 16 + bk) * N + n0 + bn;
        rb0 = *(const float4*)q;
        rb1 = *(const float4*)(q + (size_t)8 * N);
    };

    auto sts = [&](int buf) {
        if (A_KM) {
            float* s = &As[buf][ak * 136 + am];
            s[0] = to_tf32(ra0.x); s[1] = to_tf32(ra0.y);
            s[2] = to_tf32(ra0.z); s[3] = to_tf32(ra0.w);
            s += 8 * 136;
            s[0] = to_tf32(ra1.x); s[1] = to_tf32(ra1.y);
            s[2] = to_tf32(ra1.z); s[3] = to_tf32(ra1.w);
        } else {
            float* s = &As[buf][tm * 20 + tk];
            s[0] = to_tf32(ra0.x); s[1] = to_tf32(ra0.y);
            s[2] = to_tf32(ra0.z); s[3] = to_tf32(ra0.w);
            s = &As[buf][(tm + 64) * 20 + tk];
            s[0] = to_tf32(ra1.x); s[1] = to_tf32(ra1.y);
            s[2] = to_tf32(ra1.z); s[3] = to_tf32(ra1.w);
        }
        float* u = &Bs[buf][bk * 136 + bn];
        u[0] = to_tf32(rb0.x); u[1] = to_tf32(rb0.y);
        u[2] = to_tf32(rb0.z); u[3] = to_tf32(rb0.w);
        u += 8 * 136;
        u[0] = to_tf32(rb1.x); u[1] = to_tf32(rb1.y);
        u[2] = to_tf32(rb1.z); u[3] = to_tf32(rb1.w);
    };

    const int KT = K >> 4;
    ldg(0);
    sts(0);
    __syncthreads();

    for (int kt = 0; kt < KT; kt++) {
        const int cur = kt & 1;
        if (kt + 1 < KT) ldg(kt + 1);

        #pragma unroll
        for (int ks = 0; ks < 2; ks++) {
            const int k0 = ks * 8;
            uint32_t af[2][4], bf[8][2];
            #pragma unroll
            for (int mt = 0; mt < 2; mt++) {
                const int mm = wm + mt * 16 + r;
                if (A_KM) {
                    af[mt][0] = __float_as_uint(As[cur][(k0 + cq) * 136 + mm]);
                    af[mt][1] = __float_as_uint(As[cur][(k0 + cq) * 136 + mm + 8]);
                    af[mt][2] = __float_as_uint(As[cur][(k0 + cq + 4) * 136 + mm]);
                    af[mt][3] = __float_as_uint(As[cur][(k0 + cq + 4) * 136 + mm + 8]);
                } else {
                    af[mt][0] = __float_as_uint(As[cur][mm * 20 + k0 + cq]);
                    af[mt][1] = __float_as_uint(As[cur][(mm + 8) * 20 + k0 + cq]);
                    af[mt][2] = __float_as_uint(As[cur][mm * 20 + k0 + cq + 4]);
                    af[mt][3] = __float_as_uint(As[cur][(mm + 8) * 20 + k0 + cq + 4]);
                }
            }
            #pragma unroll
            for (int nt = 0; nt < 8; nt++) {
                const int nn = wn + nt * 8 + r;
                bf[nt][0] = __float_as_uint(Bs[cur][(k0 + cq) * 136 + nn]);
                bf[nt][1] = __float_as_uint(Bs[cur][(k0 + cq + 4) * 136 + nn]);
            }
            #pragma unroll
            for (int mt = 0; mt < 2; mt++)
                #pragma unroll
                for (int nt = 0; nt < 8; nt++)
                    mma_tf32(acc[mt][nt], af[mt], bf[nt]);
        }

        if (kt + 1 < KT) sts((kt + 1) & 1);
        __syncthreads();
    }

    // epilogue: row-major float2 stores
    #pragma unroll
    for (int mt = 0; mt < 2; mt++) {
        #pragma unroll
        for (int h = 0; h < 2; h++) {
            const int row = m0 + wm + mt * 16 + r + h * 8;
            float bb = (EPI == 1) ? bias[row] : 0.f;
            #pragma unroll
            for (int nt = 0; nt < 8; nt++) {
                const int col = n0 + wn + nt * 8 + cq * 2;
                float v0 = acc[mt][nt][h * 2 + 0];
                float v1 = acc[mt][nt][h * 2 + 1];
                if (EPI == 1) { v0 = softplus_f(v0 + bb); v1 = softplus_f(v1 + bb); }
                float2 o; o.x = v0; o.y = v1;
                *(float2*)(C + (size_t)row * N + col) = o;
            }
        }
    }
}

// ---------------- depthwise causal conv (k=4) + SiLU, plus silu(z); write transposed
__global__ __launch_bounds__(256) void conv_kernel(
    const float* __restrict__ cw, const float* __restrict__ cb)
{
    __shared__ float sx[32][69];
    __shared__ float sz[32][65];
    const int tid = threadIdx.x;
    const int d0 = blockIdx.x * 32;
    const int t0 = blockIdx.y * 64;
    const int b  = blockIdx.z;

    for (int idx = tid; idx < 32 * 67; idx += 256) {
        int tt = idx >> 5, dd = idx & 31;
        int t = t0 + tt - 3;
        float v = 0.f;
        if (t >= 0) v = g_xz[((size_t)(b * TLEN + t)) * (2 * DIMD) + d0 + dd];
        sx[dd][tt] = v;
    }
    for (int idx = tid; idx < 32 * 64; idx += 256) {
        int tt = idx >> 5, dd = idx & 31;
        sz[dd][tt] = g_xz[((size_t)(b * TLEN + t0 + tt)) * (2 * DIMD) + DIMD + d0 + dd];
    }
    __syncthreads();

    const int dd = tid >> 3;
    const int tb = (tid & 7) * 8;
    const int d  = d0 + dd;
    const float w0 = cw[d * 4 + 0], w1 = cw[d * 4 + 1];
    const float w2 = cw[d * 4 + 2], w3 = cw[d * 4 + 3];
    const float bsv = cb[d];
    const size_t obase = (size_t)d * MROWS + (size_t)b * TLEN + t0 + tb;
    #pragma unroll
    for (int i = 0; i < 8; i++) {
        int tt = tb + i;
        float a = bsv + w0 * sx[dd][tt] + w1 * sx[dd][tt + 1]
                      + w2 * sx[dd][tt + 2] + w3 * sx[dd][tt + 3];
        g_xactT[obase + i] = a / (1.f + __expf(-a));
        float z = sz[dd][tt];
        g_szT[obase + i] = z / (1.f + __expf(-z));
    }
}

// ---------------- BC = x_act @ W_x (K-major A), out (m, 32) -----------------
__global__ __launch_bounds__(256) void bc_kernel(const float* __restrict__ Wx)
{
    __shared__ float xs[32][64];
    __shared__ float ws[32][32];
    const int tid = threadIdx.x;
    const int m0 = blockIdx.x * 64;
    const int n = tid & 31;
    const int mb = (tid >> 5) * 8;
    float acc[8];
    #pragma unroll
    for (int i = 0; i < 8; i++) acc[i] = 0.f;

    for (int d0 = 0; d0 < DIMD; d0 += 32) {
        #pragma unroll
        for (int r = 0; r < 8; r++) {
            int idx = tid + r * 256;
            int dd = idx >> 6, mm = idx & 63;
            xs[dd][mm] = g_xactT[(size_t)(d0 + dd) * MROWS + m0 + mm];
        }
        #pragma unroll
        for (int r = 0; r < 4; r++) {
            int idx = tid + r * 256;
            int dd = idx >> 5, nn = idx & 31;
            ws[dd][nn] = Wx[(d0 + dd) * 32 + nn];
        }
        __syncthreads();
        #pragma unroll
        for (int dd = 0; dd < 32; dd++) {
            float w = ws[dd][n];
            #pragma unroll
            for (int i = 0; i < 8; i++)
                acc[i] = fmaf(xs[dd][mb + i], w, acc[i]);
        }
        __syncthreads();
    }
    #pragma unroll
    for (int i = 0; i < 8; i++)
        g_BC[(size_t)(m0 + mb + i) * 32 + n] = acc[i];
}

// ---------------- selective scan: one thread per (b, d, n) ------------------
__global__ __launch_bounds__(256) void scan_kernel(
    const float* __restrict__ A_log, const float* __restrict__ Dpar)
{
    const int g = blockIdx.x * blockDim.x + threadIdx.x;  // 0..32767
    const int n = g & (NST - 1);
    const int bd = g >> 4;
    const int d = bd & (DIMD - 1);
    const int b = bd >> 10;

    const float Adn = -expf(A_log[d * NST + n]);
    const float Dp = Dpar[d];
    const size_t rb = (size_t)d * MROWS + (size_t)b * TLEN;
    const float* bc = g_BC + (size_t)b * TLEN * 32;

    float h = 0.f;
    for (int t0 = 0; t0 < TLEN; t0 += 16) {
        float dtv = g_dtT[rb + t0 + n];
        float xv  = g_xactT[rb + t0 + n];
        float ybuf = 0.f;
        #pragma unroll
        for (int k = 0; k < 16; k++) {
            float dtk = __shfl_sync(0xffffffffu, dtv, k, 16);
            float xk  = __shfl_sync(0xffffffffu, xv,  k, 16);
            float Bv = bc[(t0 + k) * 32 + n];
            float Cv = bc[(t0 + k) * 32 + NST + n];
            float a = __expf(dtk * Adn);
            h = fmaf(a, h, dtk * Bv * xk);
            float p = h * Cv;
            p += __shfl_xor_sync(0xffffffffu, p, 1, 16);
            p += __shfl_xor_sync(0xffffffffu, p, 2, 16);
            p += __shfl_xor_sync(0xffffffffu, p, 4, 16);
            p += __shfl_xor_sync(0xffffffffu, p, 8, 16);
            if (k == n) ybuf = fmaf(Dp, xk, p);
        }
        float sv = g_szT[rb + t0 + n];
        g_yT[rb + t0 + n] = ybuf * sv;
    }
}

// ---------------- launch ----------------------------------------------------
extern "C" void kernel_launch(void* const* d_in, const int* in_sizes, int n_in,
                              void* d_out, int out_size)
{
    const float* x      = (const float*)d_in[0];
    const float* W_in   = (const float*)d_in[1];
    const float* conv_w = (const float*)d_in[2];
    const float* conv_b = (const float*)d_in[3];
    const float* A_log  = (const float*)d_in[4];
    const float* D_par  = (const float*)d_in[5];
    const float* W_x    = (const float*)d_in[6];
    const float* W_dt   = (const float*)d_in[7];
    const float* b_dt   = (const float*)d_in[8];
    const float* W_out  = (const float*)d_in[9];
    float* out = (float*)d_out;

    float *p_xz, *p_xactT, *p_dtT, *p_yT;
    cudaGetSymbolAddress((void**)&p_xz,    g_xz);
    cudaGetSymbolAddress((void**)&p_xactT, g_xactT);
    cudaGetSymbolAddress((void**)&p_dtT,   g_dtT);
    cudaGetSymbolAddress((void**)&p_yT,    g_yT);

    // 1) xz = x @ W_in   (M=8192, N=2048, K=1024), A row-major
    {
        dim3 grid(2 * DIMD / 128, MROWS / 128);
        tgemm<false, 0><<<grid, 256>>>(x, W_in, p_xz, nullptr,
                                       MROWS, 2 * DIMD, DIMD);
    }
    // 2) depthwise conv + SiLU (-> xactT), silu(z) (-> szT)
    {
        dim3 grid(DIMD / 32, TLEN / 64, BSZ);
        conv_kernel<<<grid, 256>>>(conv_w, conv_b);
    }
    // 3) BC = x_act @ W_x  (8192 x 32)
    bc_kernel<<<MROWS / 64, 256>>>(W_x);
    // 4) dtT[e][m] = softplus( sum_d W_dt[d][e] * xactT[d][m] + b_dt[e] )
    //    -> GEMM with M=1024 (e), N=8192 (m), K=1024 (d); A = W_dt stored [K][M]
    {
        dim3 grid(MROWS / 128, DIMD / 128);
        tgemm<true, 1><<<grid, 256>>>(W_dt, p_xactT, p_dtT, b_dt,
                                      DIMD, MROWS, DIMD);
    }
    // 5) selective scan -> yT (includes *silu(z))
    scan_kernel<<<(BSZ * DIMD * NST) / 256, 256>>>(A_log, D_par);
    // 6) out = y @ W_out  (M=8192, N=1024, K=1024), A = yT stored [K][M]
    {
        dim3 grid(DIMD / 128, MROWS / 128);
        tgemm<true, 0><<<grid, 256>>>(p_yT, W_out, out, nullptr,
                                      MROWS, DIMD, DIMD);
    }
}